// round 1
// baseline (speedup 1.0000x reference)
#include <cuda_runtime.h>
#include <cstdint>

#define NODES   64
#define NINPUT  16
#define NOUT    8
#define NEDGE   256
#define BATCH   8192
#define PASSES  64
#define T       64            // batch columns (= threads) per block
#define GRIDB   (BATCH / T)   // 128 blocks
#define G       8             // edges per independent chunk
#define MAXSLOTS 2048         // worst case: 256 levels * 8 (provably sufficient)

__device__ uint2 g_recs[MAXSLOTS];
__device__ int   g_nchunks;

// ---------------------------------------------------------------------------
// Scheduler: levelize the 256-edge sequence so that edges within one chunk of
// G=8 are pairwise hazard-free (no RAW/WAW/WAR), preserving exact semantics.
// Runs as 1 warp; ~10us. Emits padded edge records {dst_off<<16|src_off, w*2log2e}.
// ---------------------------------------------------------------------------
__global__ void sched_kernel(const float* __restrict__ w,
                             const int*   __restrict__ src,
                             const int*   __restrict__ dst) {
    __shared__ int   ss[NEDGE], sd[NEDGE], lvl[NEDGE];
    __shared__ float sw[NEDGE];
    __shared__ int   cnt[NEDGE], off[NEDGE];
    __shared__ int   s_total;
    const int lane = threadIdx.x;

    for (int e = lane; e < NEDGE; e += 32) {
        ss[e] = src[e]; sd[e] = dst[e]; sw[e] = w[e]; cnt[e] = 0;
    }
    __syncwarp();

    // Sequential DP over edges; warp-parallel scan of predecessors.
    for (int e = 0; e < NEDGE; e++) {
        const int se = ss[e], de = sd[e];
        int m = -1;
        for (int t = lane; t < e; t += 32) {
            // hazard: t writes my src (RAW), t writes my dst (WAW/accum order),
            //         t reads my dst (WAR)
            if (sd[t] == se || sd[t] == de || ss[t] == de) {
                int l = lvl[t];
                if (l > m) m = l;
            }
        }
        m = __reduce_max_sync(0xffffffffu, m);
        if (lane == 0) lvl[e] = m + 1;
        __syncwarp();
    }

    // per-level counts
    for (int e = lane; e < NEDGE; e += 32) atomicAdd(&cnt[lvl[e]], 1);
    __syncwarp();

    // offsets, padded to multiples of G
    if (lane == 0) {
        int o = 0;
        for (int l = 0; l < NEDGE; l++) { off[l] = o; o += (cnt[l] + (G - 1)) & ~(G - 1); }
        s_total   = o;
        g_nchunks = o / G;
    }
    __syncwarp();

    // fill padding slots with dummy edges (scratch row NODES, weight 0 -> adds 0)
    const unsigned scr = (unsigned)(NODES * T);
    uint2 dummy; dummy.x = (scr << 16) | scr; dummy.y = __float_as_uint(0.0f);
    for (int l = lane; l < NEDGE; l += 32) {
        const int c = cnt[l];
        if (c > 0) {
            const int padded = (c + (G - 1)) & ~(G - 1);
            for (int s = off[l] + c; s < off[l] + padded; s++) g_recs[s] = dummy;
        }
    }

    // emit real edges, stable order within level
    const float K2 = 2.8853900817779268f;  // 2 * log2(e)
    for (int e = lane; e < NEDGE; e += 32) {
        const int le = lvl[e];
        int r = 0;
        for (int t = 0; t < e; t++) r += (lvl[t] == le);
        const unsigned so = (unsigned)(ss[e] * T);
        const unsigned dofs = (unsigned)(sd[e] * T);
        uint2 rec;
        rec.x = (dofs << 16) | so;
        rec.y = __float_as_uint(sw[e] * K2);
        g_recs[off[le] + r] = rec;
    }
    (void)s_total;
}

// ---------------------------------------------------------------------------
// Main kernel: one thread = one batch column. Node state [65 rows x T cols]
// in shared memory (row 64 = scratch for dummy edges). Chunks of 8 hazard-free
// edges: batched loads -> 8 independent tanh chains -> batched RMW stores.
// tanh(x) = 1 - 2/(exp2(x*2log2e) + 1) via MUFU ex2/rcp (~1e-6 per-op error).
// ---------------------------------------------------------------------------
__global__ void __launch_bounds__(T, 1)
net_kernel(const float* __restrict__ x, float* __restrict__ out) {
    __shared__ float vals[(NODES + 1) * T];
    __shared__ uint2 recs[MAXSLOTS];

    const int tid = threadIdx.x;
    const int col = blockIdx.x * T + tid;

    const int nch   = g_nchunks;
    const int slots = nch * G;
    for (int s = tid; s < slots; s += T) recs[s] = g_recs[s];

    #pragma unroll
    for (int r = 0; r < NINPUT; r++) vals[r * T + tid] = x[r * BATCH + col];
    #pragma unroll
    for (int r = NINPUT; r <= NODES; r++) vals[r * T + tid] = 0.0f;
    __syncthreads();

    float* base = vals + tid;

    #pragma unroll 1
    for (int p = 0; p < PASSES; p++) {
        #pragma unroll 1
        for (int c = 0; c < nch; c++) {
            const uint2* rp = &recs[c * G];
            float    v[G], wv[G], pv[G];
            unsigned dofs[G];
            #pragma unroll
            for (int i = 0; i < G; i++) {
                const uint2 rr = rp[i];
                const unsigned so = rr.x & 0xffffu;
                dofs[i] = rr.x >> 16;
                wv[i]   = __uint_as_float(rr.y);
                v[i]    = base[so];        // src values (no RAW within chunk)
                pv[i]   = base[dofs[i]];   // dst values (dsts distinct in chunk)
            }
            #pragma unroll
            for (int i = 0; i < G; i++) {
                const float a = v[i] * wv[i];
                float ev;  asm("ex2.approx.f32 %0, %1;" : "=f"(ev) : "f"(a));
                float rr2; asm("rcp.approx.f32 %0, %1;" : "=f"(rr2) : "f"(ev + 1.0f));
                base[dofs[i]] = pv[i] + fmaf(-2.0f, rr2, 1.0f);
            }
        }
    }

    #pragma unroll
    for (int r = 0; r < NOUT; r++) {
        out[r * BATCH + col] = tanhf(vals[(NINPUT + r) * T + tid]);
    }
}

extern "C" void kernel_launch(void* const* d_in, const int* in_sizes, int n_in,
                              void* d_out, int out_size) {
    const float* x   = (const float*)d_in[0];
    const float* w   = (const float*)d_in[1];
    const int*   src = (const int*)d_in[2];
    const int*   dst = (const int*)d_in[3];
    (void)in_sizes; (void)n_in; (void)out_size;

    sched_kernel<<<1, 32>>>(w, src, dst);
    net_kernel<<<GRIDB, T>>>(x, (float*)d_out);
}

// round 2
// speedup vs baseline: 1.6163x; 1.6163x over previous
#include <cuda_runtime.h>
#include <cstdint>

#define NODES   64
#define NINPUT  16
#define NOUT    8
#define NEDGE   256
#define BATCH   8192
#define PASSES  64
#define T       64            // batch columns (= threads) per block
#define GRIDB   (BATCH / T)   // 128 blocks
#define G       8             // edges per hazard-free chunk
#define MAXSLOTS 2048         // worst case 256 chunks * 8

__device__ uint2 g_recs[MAXSLOTS];
__device__ int   g_nchunks;

// ---------------------------------------------------------------------------
// Scheduler: greedy list scheduling with 64-bit node masks.
// Builds chunks of G=8 pairwise hazard-free edges (RAW/WAW/WAR preserved wrt
// the sequential edge order). Thread 0 serial; ~10-20us.
// Record: x = (dst_byte_off << 16) | src_byte_off,  y = w * 2*log2(e).
// ---------------------------------------------------------------------------
__global__ void sched_kernel(const float* __restrict__ w,
                             const int*   __restrict__ src,
                             const int*   __restrict__ dst) {
    __shared__ int   ss[NEDGE], sd[NEDGE];
    __shared__ float swk[NEDGE];
    __shared__ unsigned char done[NEDGE];
    const int lane = threadIdx.x;
    const float K2 = 2.8853900817779268f;  // 2 * log2(e)

    for (int e = lane; e < NEDGE; e += 32) {
        ss[e]   = src[e];
        sd[e]   = dst[e];
        swk[e]  = w[e] * K2;
        done[e] = 0;
    }
    __syncwarp();

    if (lane == 0) {
        const unsigned scr = (unsigned)(NODES * T * 4);  // scratch row byte off
        uint2 dummy;
        dummy.x = (scr << 16) | scr;
        dummy.y = __float_as_uint(0.0f);

        int head = 0, nsch = 0, slot = 0;
        while (nsch < NEDGE) {
            unsigned long long Wm = 0ull, Rm = 0ull;
            int members = 0;
            for (int e = head; e < NEDGE && members < G; e++) {
                if (done[e]) continue;
                const int s = ss[e], d = sd[e];
                const bool ok = !((Wm >> s) & 1ull) &&
                                !((Wm >> d) & 1ull) &&
                                !((Rm >> d) & 1ull);
                // Footprint added either way: members block conflicts inside
                // the chunk; skipped edges block later conflicting edges
                // (preserves program order across the skip).
                Wm |= 1ull << d;
                Rm |= 1ull << s;
                if (ok) {
                    uint2 rec;
                    rec.x = ((unsigned)(d * T * 4) << 16) | (unsigned)(s * T * 4);
                    rec.y = __float_as_uint(swk[e]);
                    g_recs[slot++] = rec;
                    done[e] = 1;
                    nsch++;
                    members++;
                }
            }
            for (; members < G; members++) g_recs[slot++] = dummy;
            while (head < NEDGE && done[head]) head++;
        }
        g_nchunks = slot / G;
    }
}

// ---------------------------------------------------------------------------
// Main kernel: one thread = one batch column. Node state [65 rows x T cols]
// in smem (row 64 = scratch for dummy slots). Per chunk: 8x batched loads
// (src, dst+1.0f), then 8 independent tanh chains + stores.
// tanh(x) = 1 - 2/(exp2(x*2log2e)+1) via MUFU ex2/rcp (~1e-6 per-op error).
// ---------------------------------------------------------------------------
__global__ void __launch_bounds__(T, 1)
net_kernel(const float* __restrict__ x, float* __restrict__ out) {
    __shared__ float vals[(NODES + 1) * T];
    __shared__ uint2 recs[MAXSLOTS];

    const int tid = threadIdx.x;
    const int col = blockIdx.x * T + tid;

    const int nch   = g_nchunks;
    const int slots = nch * G;
    for (int s = tid; s < slots; s += T) recs[s] = g_recs[s];

    #pragma unroll
    for (int r = 0; r < NINPUT; r++) vals[r * T + tid] = x[r * BATCH + col];
    #pragma unroll
    for (int r = NINPUT; r <= NODES; r++) vals[r * T + tid] = 0.0f;
    __syncthreads();

    char* base = (char*)vals + tid * 4;

    #pragma unroll 1
    for (int p = 0; p < PASSES; p++) {
        #pragma unroll 1
        for (int c = 0; c < nch; c++) {
            const uint2* rp = &recs[c * G];
            float    v[G], wv[G], t1[G];
            unsigned db[G];
            #pragma unroll
            for (int i = 0; i < G; i++) {
                const uint2 rr = rp[i];
                const unsigned sb = rr.x & 0xffffu;
                db[i] = rr.x >> 16;
                wv[i] = __uint_as_float(rr.y);
                v[i]  = *(const float*)(base + sb);       // src (no RAW in chunk)
                t1[i] = *(const float*)(base + db[i]) + 1.0f;  // dst + 1
            }
            #pragma unroll
            for (int i = 0; i < G; i++) {
                const float a = v[i] * wv[i];
                float ev;  asm("ex2.approx.f32 %0, %1;" : "=f"(ev) : "f"(a));
                float rr2; asm("rcp.approx.f32 %0, %1;" : "=f"(rr2) : "f"(ev + 1.0f));
                // dst_new = pv + (1 - 2/(ev+1)) = fma(-2, r, pv+1)
                *(float*)(base + db[i]) = fmaf(-2.0f, rr2, t1[i]);
            }
        }
    }

    #pragma unroll
    for (int r = 0; r < NOUT; r++) {
        out[r * BATCH + col] = tanhf(vals[(NINPUT + r) * T + tid]);
    }
}

extern "C" void kernel_launch(void* const* d_in, const int* in_sizes, int n_in,
                              void* d_out, int out_size) {
    const float* x   = (const float*)d_in[0];
    const float* w   = (const float*)d_in[1];
    const int*   src = (const int*)d_in[2];
    const int*   dst = (const int*)d_in[3];
    (void)in_sizes; (void)n_in; (void)out_size;

    sched_kernel<<<1, 32>>>(w, src, dst);
    net_kernel<<<GRIDB, T>>>(x, (float*)d_out);
}